// round 10
// baseline (speedup 1.0000x reference)
#include <cuda_runtime.h>
#include <cstdint>

// out[n, d, b] = unique_weights[indices[n], d] * input_values[n, d, b]
// N=16384, U=1024, D=128, B=16, fp32.  256 MiB compulsory HBM traffic.
//
// R7 (bulk TMA reads, STG writes): 41.7us, DRAM 65%. This round: symmetric
// bulk WRITES too. Each CTA: TMA bulk G2S 16 KiB tile -> in-place multiply in
// SMEM -> TMA bulk S2G 16 KiB tile. Depth-2 ring, 6 CTAs/SM.

#define N_POS 16384
#define U_DIM 1024
#define D_DIM 128
#define B_DIM 16

#define TILE_BYTES  16384                 // 16 KiB per bulk copy
#define TILE_F4     (TILE_BYTES / 16)     // 1024 float4 per tile
#define THREADS     256                   // 4 float4 per thread per tile
#define N_TILES     (N_POS * D_DIM * B_DIM * 4 / TILE_BYTES)  // 8192

__device__ __forceinline__ uint32_t smem_u32(const void* p) {
    uint32_t a;
    asm("{ .reg .u64 t; cvta.to.shared.u64 t, %1; cvt.u32.u64 %0, t; }"
        : "=r"(a) : "l"(p));
    return a;
}

__device__ __forceinline__ void mbar_init(uint32_t mbar, uint32_t count) {
    asm volatile("mbarrier.init.shared.b64 [%0], %1;" :: "r"(mbar), "r"(count) : "memory");
}

__device__ __forceinline__ void mbar_expect_tx(uint32_t mbar, uint32_t bytes) {
    asm volatile("mbarrier.arrive.expect_tx.shared.b64 _, [%0], %1;"
                 :: "r"(mbar), "r"(bytes) : "memory");
}

__device__ __forceinline__ void bulk_g2s(uint32_t dst_smem, const void* src_gmem,
                                         uint32_t bytes, uint32_t mbar) {
    asm volatile("cp.async.bulk.shared::cluster.global.mbarrier::complete_tx::bytes "
                 "[%0], [%1], %2, [%3];"
                 :: "r"(dst_smem), "l"(src_gmem), "r"(bytes), "r"(mbar) : "memory");
}

__device__ __forceinline__ void bulk_s2g(void* dst_gmem, uint32_t src_smem,
                                         uint32_t bytes) {
    asm volatile("cp.async.bulk.global.shared::cta.bulk_group [%0], [%1], %2;"
                 :: "l"(dst_gmem), "r"(src_smem), "r"(bytes) : "memory");
}

__device__ __forceinline__ void store_commit() {
    asm volatile("cp.async.bulk.commit_group;" ::: "memory");
}

__device__ __forceinline__ void store_wait_read_all() {
    asm volatile("cp.async.bulk.wait_group.read 0;" ::: "memory");
}

__device__ __forceinline__ void store_wait_all() {
    asm volatile("cp.async.bulk.wait_group 0;" ::: "memory");
}

__device__ __forceinline__ void fence_proxy_async_shared() {
    asm volatile("fence.proxy.async.shared::cta;" ::: "memory");
}

__device__ __forceinline__ void mbar_wait(uint32_t mbar, uint32_t parity) {
    asm volatile(
        "{\n\t"
        ".reg .pred P;\n\t"
        "WAIT_%=:\n\t"
        "mbarrier.try_wait.parity.acquire.cta.shared::cta.b64 P, [%0], %1, 0x989680;\n\t"
        "@P bra.uni DONE_%=;\n\t"
        "bra.uni WAIT_%=;\n\t"
        "DONE_%=:\n\t"
        "}"
        :: "r"(mbar), "r"(parity) : "memory");
}

__global__ void __launch_bounds__(THREADS) diag_scale_tma2_kernel(
    const float* __restrict__ x,          // [N, D, B]
    const float* __restrict__ w,          // [U, D]
    const int* __restrict__ idx,          // [N] (int32)
    float* __restrict__ out)              // [N, D, B]
{
    __shared__ alignas(128) float4 buf[2][TILE_F4];   // 2 x 16 KiB
    __shared__ alignas(8) unsigned long long mbar_s[2];

    const int tid = threadIdx.x;
    const uint32_t mba[2] = { smem_u32(&mbar_s[0]), smem_u32(&mbar_s[1]) };
    const uint32_t bufa[2] = { smem_u32(&buf[0][0]), smem_u32(&buf[1][0]) };

    if (tid == 0) {
        mbar_init(mba[0], 1);
        mbar_init(mba[1], 1);
    }
    __syncthreads();

    const int G = gridDim.x;
    const int t0 = blockIdx.x;

    // Prologue: prefetch first two tiles.
    if (tid == 0) {
        if (t0 < N_TILES) {
            mbar_expect_tx(mba[0], TILE_BYTES);
            bulk_g2s(bufa[0], (const char*)x + (size_t)t0 * TILE_BYTES, TILE_BYTES, mba[0]);
        }
        if (t0 + G < N_TILES) {
            mbar_expect_tx(mba[1], TILE_BYTES);
            bulk_g2s(bufa[1], (const char*)x + (size_t)(t0 + G) * TILE_BYTES, TILE_BYTES, mba[1]);
        }
    }

    int ph[2] = {0, 0};
    int k = 0;
    for (int t = t0; t < N_TILES; t += G, k++) {
        const int s = k & 1;

        // Wait for this tile's data.
        mbar_wait(mba[s], ph[s]);
        ph[s] ^= 1;

        float4* __restrict__ bp = buf[s];
        const unsigned int gbase = (unsigned int)t * TILE_F4;

        // In-place: load 4 float4, scale, store back to SMEM.
        float4 v[4];
        float  wv[4];
        #pragma unroll
        for (int j = 0; j < 4; j++) {
            const int f4i = tid + j * THREADS;
            v[j] = bp[f4i];
            const unsigned int row = (gbase + (unsigned int)f4i) >> 2;  // 4 f4 per row
            const unsigned int n = row >> 7;
            const unsigned int d = row & 127;
            const unsigned int u = (unsigned int)__ldg(&idx[n]) & (U_DIM - 1);
            wv[j] = __ldg(&w[(size_t)u * D_DIM + d]);
        }
        #pragma unroll
        for (int j = 0; j < 4; j++) {
            const int f4i = tid + j * THREADS;
            float4 r = v[j];
            r.x *= wv[j]; r.y *= wv[j]; r.z *= wv[j]; r.w *= wv[j];
            bp[f4i] = r;
        }

        __syncthreads();   // all STS visible CTA-wide

        if (tid == 0) {
            fence_proxy_async_shared();                 // order STS before TMA read
            bulk_s2g((char*)out + (size_t)t * TILE_BYTES, bufa[s], TILE_BYTES);
            store_commit();

            const int tn = t + 2 * G;
            if (tn < N_TILES) {
                // Buffer s is referenced by the store just committed; wait until
                // its SMEM reads have drained before TMA load overwrites it.
                store_wait_read_all();
                mbar_expect_tx(mba[s], TILE_BYTES);
                bulk_g2s(bufa[s], (const char*)x + (size_t)tn * TILE_BYTES,
                         TILE_BYTES, mba[s]);
            }
        }
    }

    // Don't exit the CTA with bulk stores in flight.
    if (tid == 0) store_wait_all();
}

extern "C" void kernel_launch(void* const* d_in, const int* in_sizes, int n_in,
                              void* d_out, int out_size)
{
    // Bind by element count — robust to metadata ordering.
    const float* x = nullptr;    // N*D*B = 33,554,432
    const float* w = nullptr;    // U*D   = 131,072
    const int* idx = nullptr;    // N     = 16,384
    for (int i = 0; i < n_in; i++) {
        if (in_sizes[i] == N_POS * D_DIM * B_DIM)   x   = (const float*)d_in[i];
        else if (in_sizes[i] == U_DIM * D_DIM)      w   = (const float*)d_in[i];
        else if (in_sizes[i] == N_POS)              idx = (const int*)d_in[i];
    }
    float* out = (float*)d_out;

    // 8192 tiles / 1024 CTAs = exactly 8 tiles per CTA.
    const int blocks = 1024;
    diag_scale_tma2_kernel<<<blocks, THREADS>>>(x, w, idx, out);
}

// round 11
// speedup vs baseline: 1.0795x; 1.0795x over previous
#include <cuda_runtime.h>
#include <cstdint>

// out[n, d, b] = unique_weights[indices[n], d] * input_values[n, d, b]
// N=16384, U=1024, D=128, B=16, fp32.  256 MiB compulsory HBM traffic.
//
// Winning structure (R7, 41.7us): bulk TMA G2S reads (16 KiB grain) + plain
// coalesced STG.128 writes. Bulk S2G writes proven worse (R10: serializes the
// ring). This round: depth-3 ring (3 x 16 KiB, 4 CTAs/SM) so 2 loads stay in
// flight per CTA during compute.

#define N_POS 16384
#define U_DIM 1024
#define D_DIM 128
#define B_DIM 16

#define TILE_BYTES  16384                 // 16 KiB per bulk copy
#define TILE_F4     (TILE_BYTES / 16)     // 1024 float4 per tile
#define THREADS     256                   // 4 float4 per thread per tile
#define DEPTH       3
#define N_TILES     (N_POS * D_DIM * B_DIM * 4 / TILE_BYTES)  // 8192

__device__ __forceinline__ uint32_t smem_u32(const void* p) {
    uint32_t a;
    asm("{ .reg .u64 t; cvta.to.shared.u64 t, %1; cvt.u32.u64 %0, t; }"
        : "=r"(a) : "l"(p));
    return a;
}

__device__ __forceinline__ void mbar_init(uint32_t mbar, uint32_t count) {
    asm volatile("mbarrier.init.shared.b64 [%0], %1;" :: "r"(mbar), "r"(count) : "memory");
}

__device__ __forceinline__ void mbar_expect_tx(uint32_t mbar, uint32_t bytes) {
    asm volatile("mbarrier.arrive.expect_tx.shared.b64 _, [%0], %1;"
                 :: "r"(mbar), "r"(bytes) : "memory");
}

__device__ __forceinline__ void bulk_g2s(uint32_t dst_smem, const void* src_gmem,
                                         uint32_t bytes, uint32_t mbar) {
    asm volatile("cp.async.bulk.shared::cluster.global.mbarrier::complete_tx::bytes "
                 "[%0], [%1], %2, [%3];"
                 :: "r"(dst_smem), "l"(src_gmem), "r"(bytes), "r"(mbar) : "memory");
}

__device__ __forceinline__ void mbar_wait(uint32_t mbar, uint32_t parity) {
    asm volatile(
        "{\n\t"
        ".reg .pred P;\n\t"
        "WAIT_%=:\n\t"
        "mbarrier.try_wait.parity.acquire.cta.shared::cta.b64 P, [%0], %1, 0x989680;\n\t"
        "@P bra.uni DONE_%=;\n\t"
        "bra.uni WAIT_%=;\n\t"
        "DONE_%=:\n\t"
        "}"
        :: "r"(mbar), "r"(parity) : "memory");
}

__global__ void __launch_bounds__(THREADS) diag_scale_tma3_kernel(
    const float* __restrict__ x,          // [N, D, B]
    const float* __restrict__ w,          // [U, D]
    const int* __restrict__ idx,          // [N] (int32)
    float* __restrict__ out)              // [N, D, B]
{
    __shared__ alignas(128) float4 buf[DEPTH][TILE_F4];   // 3 x 16 KiB
    __shared__ alignas(8) unsigned long long mbar_s[DEPTH];

    const int tid = threadIdx.x;
    uint32_t mba[DEPTH], bufa[DEPTH];
    #pragma unroll
    for (int i = 0; i < DEPTH; i++) {
        mba[i]  = smem_u32(&mbar_s[i]);
        bufa[i] = smem_u32(&buf[i][0]);
    }

    if (tid == 0) {
        #pragma unroll
        for (int i = 0; i < DEPTH; i++) mbar_init(mba[i], 1);
    }
    __syncthreads();

    const int G = gridDim.x;
    const int t0 = blockIdx.x;

    // Prologue: prefetch first DEPTH tiles.
    if (tid == 0) {
        #pragma unroll
        for (int i = 0; i < DEPTH; i++) {
            const int t = t0 + i * G;
            if (t < N_TILES) {
                mbar_expect_tx(mba[i], TILE_BYTES);
                bulk_g2s(bufa[i], (const char*)x + (size_t)t * TILE_BYTES,
                         TILE_BYTES, mba[i]);
            }
        }
    }

    int ph[DEPTH] = {0, 0, 0};
    int k = 0;
    for (int t = t0; t < N_TILES; t += G, k++) {
        const int s = k % DEPTH;

        // Wait for this tile's data.
        mbar_wait(mba[s], ph[s]);
        ph[s] ^= 1;

        const float4* __restrict__ bp = buf[s];
        float4* __restrict__ op = reinterpret_cast<float4*>(out) + (size_t)t * TILE_F4;
        const unsigned int gbase = (unsigned int)t * TILE_F4;

        // 4 float4 per thread; consecutive lanes -> consecutive 16B
        // (conflict-free LDS.128, fully coalesced STG.128).
        float4 v[4];
        float  wv[4];
        #pragma unroll
        for (int j = 0; j < 4; j++) {
            const int f4i = tid + j * THREADS;
            v[j] = bp[f4i];
            const unsigned int row = (gbase + (unsigned int)f4i) >> 2;  // 4 f4 per row
            const unsigned int n = row >> 7;
            const unsigned int d = row & 127;
            const unsigned int u = (unsigned int)__ldg(&idx[n]) & (U_DIM - 1);
            wv[j] = __ldg(&w[(size_t)u * D_DIM + d]);
        }
        #pragma unroll
        for (int j = 0; j < 4; j++) {
            const int f4i = tid + j * THREADS;
            float4 r = v[j];
            r.x *= wv[j]; r.y *= wv[j]; r.z *= wv[j]; r.w *= wv[j];
            op[f4i] = r;
        }

        __syncthreads();   // everyone done reading buf[s]; safe to refill

        const int tn = t + DEPTH * G;
        if (tn < N_TILES && tid == 0) {
            mbar_expect_tx(mba[s], TILE_BYTES);
            bulk_g2s(bufa[s], (const char*)x + (size_t)tn * TILE_BYTES,
                     TILE_BYTES, mba[s]);
        }
    }
}

extern "C" void kernel_launch(void* const* d_in, const int* in_sizes, int n_in,
                              void* d_out, int out_size)
{
    // Bind by element count — robust to metadata ordering.
    const float* x = nullptr;    // N*D*B = 33,554,432
    const float* w = nullptr;    // U*D   = 131,072
    const int* idx = nullptr;    // N     = 16,384
    for (int i = 0; i < n_in; i++) {
        if (in_sizes[i] == N_POS * D_DIM * B_DIM)   x   = (const float*)d_in[i];
        else if (in_sizes[i] == U_DIM * D_DIM)      w   = (const float*)d_in[i];
        else if (in_sizes[i] == N_POS)              idx = (const int*)d_in[i];
    }
    float* out = (float*)d_out;

    // 8192 tiles / 1024 CTAs = exactly 8 tiles per CTA; 4 CTAs/SM (48 KiB smem).
    const int blocks = 1024;
    diag_scale_tma3_kernel<<<blocks, THREADS>>>(x, w, idx, out);
}

// round 12
// speedup vs baseline: 1.0853x; 1.0054x over previous
#include <cuda_runtime.h>
#include <cstdint>

// out[n, d, b] = unique_weights[indices[n], d] * input_values[n, d, b]
// N=16384, U=1024, D=128, B=16, fp32.  256 MiB compulsory HBM traffic.
//
// Winning structure (R7, 41.7us kernel, DRAM 65%): bulk TMA G2S reads + plain
// coalesced STG.128 writes; depth-2 ring. R11 showed per-CTA depth trades
// against CTA count and loses. This round: 8 KiB tiles (depth-2 = 16 KiB/CTA)
// so CTAs/SM is thread-capped at 8 (2048 threads) instead of smem-capped at
// ~6 -> more independent TMA streams chip-wide.

#define N_POS 16384
#define U_DIM 1024
#define D_DIM 128
#define B_DIM 16

#define TILE_BYTES  8192                  // 8 KiB per bulk copy
#define TILE_F4     (TILE_BYTES / 16)     // 512 float4 per tile
#define THREADS     256                   // 2 float4 per thread per tile
#define N_TILES     (N_POS * D_DIM * B_DIM * 4 / TILE_BYTES)  // 16384

__device__ __forceinline__ uint32_t smem_u32(const void* p) {
    uint32_t a;
    asm("{ .reg .u64 t; cvta.to.shared.u64 t, %1; cvt.u32.u64 %0, t; }"
        : "=r"(a) : "l"(p));
    return a;
}

__device__ __forceinline__ void mbar_init(uint32_t mbar, uint32_t count) {
    asm volatile("mbarrier.init.shared.b64 [%0], %1;" :: "r"(mbar), "r"(count) : "memory");
}

__device__ __forceinline__ void mbar_expect_tx(uint32_t mbar, uint32_t bytes) {
    asm volatile("mbarrier.arrive.expect_tx.shared.b64 _, [%0], %1;"
                 :: "r"(mbar), "r"(bytes) : "memory");
}

__device__ __forceinline__ void bulk_g2s(uint32_t dst_smem, const void* src_gmem,
                                         uint32_t bytes, uint32_t mbar) {
    asm volatile("cp.async.bulk.shared::cluster.global.mbarrier::complete_tx::bytes "
                 "[%0], [%1], %2, [%3];"
                 :: "r"(dst_smem), "l"(src_gmem), "r"(bytes), "r"(mbar) : "memory");
}

__device__ __forceinline__ void mbar_wait(uint32_t mbar, uint32_t parity) {
    asm volatile(
        "{\n\t"
        ".reg .pred P;\n\t"
        "WAIT_%=:\n\t"
        "mbarrier.try_wait.parity.acquire.cta.shared::cta.b64 P, [%0], %1, 0x989680;\n\t"
        "@P bra.uni DONE_%=;\n\t"
        "bra.uni WAIT_%=;\n\t"
        "DONE_%=:\n\t"
        "}"
        :: "r"(mbar), "r"(parity) : "memory");
}

__global__ void __launch_bounds__(THREADS) diag_scale_tma8k_kernel(
    const float* __restrict__ x,          // [N, D, B]
    const float* __restrict__ w,          // [U, D]
    const int* __restrict__ idx,          // [N] (int32)
    float* __restrict__ out)              // [N, D, B]
{
    __shared__ alignas(128) float4 buf[2][TILE_F4];   // 2 x 8 KiB
    __shared__ alignas(8) unsigned long long mbar_s[2];

    const int tid = threadIdx.x;
    const uint32_t mba[2] = { smem_u32(&mbar_s[0]), smem_u32(&mbar_s[1]) };
    const uint32_t bufa[2] = { smem_u32(&buf[0][0]), smem_u32(&buf[1][0]) };

    if (tid == 0) {
        mbar_init(mba[0], 1);
        mbar_init(mba[1], 1);
    }
    __syncthreads();

    const int G = gridDim.x;
    const int t0 = blockIdx.x;

    // Prologue: prefetch first two tiles.
    if (tid == 0) {
        if (t0 < N_TILES) {
            mbar_expect_tx(mba[0], TILE_BYTES);
            bulk_g2s(bufa[0], (const char*)x + (size_t)t0 * TILE_BYTES, TILE_BYTES, mba[0]);
        }
        if (t0 + G < N_TILES) {
            mbar_expect_tx(mba[1], TILE_BYTES);
            bulk_g2s(bufa[1], (const char*)x + (size_t)(t0 + G) * TILE_BYTES, TILE_BYTES, mba[1]);
        }
    }

    int ph[2] = {0, 0};
    int k = 0;
    for (int t = t0; t < N_TILES; t += G, k++) {
        const int s = k & 1;

        // Wait for this tile's data.
        mbar_wait(mba[s], ph[s]);
        ph[s] ^= 1;

        const float4* __restrict__ bp = buf[s];
        float4* __restrict__ op = reinterpret_cast<float4*>(out) + (size_t)t * TILE_F4;
        const unsigned int gbase = (unsigned int)t * TILE_F4;

        // 2 float4 per thread; consecutive lanes -> consecutive 16B
        // (conflict-free LDS.128, fully coalesced STG.128).
        float4 v[2];
        float  wv[2];
        #pragma unroll
        for (int j = 0; j < 2; j++) {
            const int f4i = tid + j * THREADS;
            v[j] = bp[f4i];
            const unsigned int row = (gbase + (unsigned int)f4i) >> 2;  // 4 f4 per row
            const unsigned int n = row >> 7;
            const unsigned int d = row & 127;
            const unsigned int u = (unsigned int)__ldg(&idx[n]) & (U_DIM - 1);
            wv[j] = __ldg(&w[(size_t)u * D_DIM + d]);
        }
        #pragma unroll
        for (int j = 0; j < 2; j++) {
            const int f4i = tid + j * THREADS;
            float4 r = v[j];
            r.x *= wv[j]; r.y *= wv[j]; r.z *= wv[j]; r.w *= wv[j];
            op[f4i] = r;
        }

        __syncthreads();   // everyone done reading buf[s]; safe to refill

        const int tn = t + 2 * G;
        if (tn < N_TILES && tid == 0) {
            mbar_expect_tx(mba[s], TILE_BYTES);
            bulk_g2s(bufa[s], (const char*)x + (size_t)tn * TILE_BYTES,
                     TILE_BYTES, mba[s]);
        }
    }
}

extern "C" void kernel_launch(void* const* d_in, const int* in_sizes, int n_in,
                              void* d_out, int out_size)
{
    // Bind by element count — robust to metadata ordering.
    const float* x = nullptr;    // N*D*B = 33,554,432
    const float* w = nullptr;    // U*D   = 131,072
    const int* idx = nullptr;    // N     = 16,384
    for (int i = 0; i < n_in; i++) {
        if (in_sizes[i] == N_POS * D_DIM * B_DIM)   x   = (const float*)d_in[i];
        else if (in_sizes[i] == U_DIM * D_DIM)      w   = (const float*)d_in[i];
        else if (in_sizes[i] == N_POS)              idx = (const int*)d_in[i];
    }
    float* out = (float*)d_out;

    // 8 CTAs/SM x 148 SMs = 1184 resident CTAs; 16384 tiles, grid-stride.
    const int blocks = 1184;
    diag_scale_tma8k_kernel<<<blocks, THREADS>>>(x, w, idx, out);
}